// round 14
// baseline (speedup 1.0000x reference)
#include <cuda_runtime.h>
#include <cuda_bf16.h>
#include <cuda_fp16.h>
#include <mma.h>
#include <math.h>
#include <stdint.h>

using namespace nvcuda;

#define NN 50000
#define EE 800000
#define KDIM 128
#define CD 128
#define NH 8

#define BM 64        // edges per block (edge kernel)
#define AW 136       // A smem leading dim (half), full K
#define AFULL 136    // node A leading dim (bf16)
#define BLD 136      // B smem leading dim (16-bit elems)
#define PLD 132      // proj smem leading dim (floats)

// ---------------- device scratch ----------------
__device__ float g_Qh[(size_t)NN * CD];
__device__ float g_Kh[(size_t)NN * CD];
__device__ float g_Vh[(size_t)NN * CD];
__device__ float g_s[(size_t)EE * NH];     // per-edge per-head weight, CSR order
__device__ int   g_cnt[NN];
__device__ int   g_off[NN + 1];
__device__ int   g_cur[NN];
__device__ int   g_esrc[EE];               // src sorted by dst
__device__ int   g_pos[EE];                // edge -> CSR slot
// edge weights: single fp16 (0=Ew 1=Rw)
__device__ __align__(16) __half g_We[2][KDIM * CD];
// node weights: bf16 hi/lo (0=Qw 1=Kw 2=Vw)
__device__ __align__(16) __nv_bfloat16 g_Wn_h[3][KDIM * CD];
__device__ __align__(16) __nv_bfloat16 g_Wn_l[3][KDIM * CD];

__device__ __forceinline__ void cvt_split_bf(float x, __nv_bfloat16& hi, __nv_bfloat16& lo) {
    hi = __float2bfloat16(x);
    lo = __float2bfloat16(x - __bfloat162float(hi));
}
__device__ __forceinline__ void cp16(uint32_t saddr, const void* gptr) {
    asm volatile("cp.async.cg.shared.global [%0], [%1], 16;"
                 :: "r"(saddr), "l"(gptr) : "memory");
}
__device__ __forceinline__ void cp_commit() {
    asm volatile("cp.async.commit_group;" ::: "memory");
}
__device__ __forceinline__ void cp_wait_all() {
    asm volatile("cp.async.wait_group 0;" ::: "memory");
}

// ---------------- weight conversion ----------------
__global__ __launch_bounds__(256) void convert_weights_kernel(
    const float* __restrict__ Ew, const float* __restrict__ Rw,
    const float* __restrict__ Qw, const float* __restrict__ Kw,
    const float* __restrict__ Vw)
{
    int i = blockIdx.x * 256 + threadIdx.x;
    if (i >= KDIM * CD) return;
    g_We[0][i] = __float2half_rn(Ew[i]);
    g_We[1][i] = __float2half_rn(Rw[i]);
    {
        __nv_bfloat16 h, l;
        cvt_split_bf(Qw[i], h, l); g_Wn_h[0][i] = h; g_Wn_l[0][i] = l;
        cvt_split_bf(Kw[i], h, l); g_Wn_h[1][i] = h; g_Wn_l[1][i] = l;
        cvt_split_bf(Vw[i], h, l); g_Wn_h[2][i] = h; g_Wn_l[2][i] = l;
    }
}

// ---------------- CSR build ----------------
__global__ __launch_bounds__(256) void hist_kernel(const int* __restrict__ dst)
{
    int e = blockIdx.x * 256 + threadIdx.x;
    if (e < EE) atomicAdd(&g_cnt[dst[e]], 1);
}

__global__ __launch_bounds__(1024) void scan_kernel()
{
    __shared__ int part[1024];
    const int t = threadIdx.x;
    const int CHUNK = (NN + 1023) / 1024;
    const int base = t * CHUNK;
    int sum = 0;
    for (int i = 0; i < CHUNK; ++i) {
        int idx = base + i;
        if (idx < NN) sum += g_cnt[idx];
    }
    part[t] = sum;
    __syncthreads();
    for (int d = 1; d < 1024; d <<= 1) {
        int v = (t >= d) ? part[t - d] : 0;
        __syncthreads();
        part[t] += v;
        __syncthreads();
    }
    int run = (t == 0) ? 0 : part[t - 1];
    for (int i = 0; i < CHUNK; ++i) {
        int idx = base + i;
        if (idx < NN) {
            g_off[idx] = run;
            g_cur[idx] = run;
            run += g_cnt[idx];
        }
    }
    if (t == 1023) g_off[NN] = run;
}

__global__ __launch_bounds__(256) void fill_kernel(
    const int* __restrict__ src, const int* __restrict__ dst)
{
    int e = blockIdx.x * 256 + threadIdx.x;
    if (e >= EE) return;
    int pos = atomicAdd(&g_cur[dst[e]], 1);
    g_esrc[pos] = src[e];
    g_pos[e] = pos;
}

// ================= edge kernel: full-K resident, fp16 A1xB1 =================
// smem: sidx(src,dst,pos) 768 pad->1024 | A full-K (AE+AK) 34816 | B full-K (BE+BR) 69632
// proj staging (R 16896 + E 16896 = 33792) aliases the dead A region (34816).
#define ESM_SIDX  0
#define ESM_A     1024
#define ASZ       (2 * BM * AW * 2)          // 34816
#define ESM_B     (ESM_A + ASZ)
#define BSZ       (KDIM * BLD * 2)           // 34816 per matrix
#define ESM_TOTAL (ESM_B + 2 * BSZ)          // 105472
#define PROJ_R    ESM_A
#define PROJ_E    (ESM_A + 64 * PLD * 4)     // 16896 offset

__global__ __launch_bounds__(256, 2) void edge_kernel(
    const float* __restrict__ e,
    const float* __restrict__ kr,
    const int*  __restrict__ src,
    const int*  __restrict__ dst,
    const float* __restrict__ Eb,
    const float* __restrict__ Rb,
    float* __restrict__ out_e)
{
    extern __shared__ char smem[];
    int*    sidx  = reinterpret_cast<int*>(smem + ESM_SIDX);  // [src 64][dst 64][pos 64]
    __half* sAE   = reinterpret_cast<__half*>(smem + ESM_A);
    __half* sAK   = sAE + BM * AW;
    __half* sBE   = reinterpret_cast<__half*>(smem + ESM_B);
    __half* sBR   = reinterpret_cast<__half*>(smem + ESM_B + BSZ);
    float*  projR = reinterpret_cast<float*>(smem + PROJ_R);
    float*  projE = reinterpret_cast<float*>(smem + PROJ_E);

    const int tid = threadIdx.x;
    const int wid = tid >> 5;
    const int r0  = blockIdx.x * BM;

    // ---- B full-K cp.async burst: 4096 cp16, 16 per thread ----
    {
        uint32_t be = (uint32_t)__cvta_generic_to_shared(sBE);
        uint32_t br = (uint32_t)__cvta_generic_to_shared(sBR);
#pragma unroll
        for (int it = 0; it < 8; ++it) {
            int i = tid + 256 * it;            // 0..2047
            int krow = i >> 4, q = i & 15;
            size_t goff = (size_t)krow * CD + q * 8;
            uint32_t soff = (uint32_t)(krow * BLD + q * 8) * 2;
            cp16(be + soff, &g_We[0][goff]);
            cp16(br + soff, &g_We[1][goff]);
        }
        cp_commit();
    }

    if (tid < BM) {
        sidx[tid]           = src[r0 + tid];
        sidx[BM + tid]      = dst[r0 + tid];
        sidx[2 * BM + tid]  = g_pos[r0 + tid];
    }

    // ---- A full-K: load (streaming), convert, STS; 16 float4 per thread ----
#pragma unroll
    for (int j = 0; j < 8; ++j) {
        int task = tid + 256 * j;              // 0..2047
        int mat  = task >> 10;                 // 0=e, 1=kr
        int row  = (task >> 4) & 63;
        int seg  = task & 15;                  // 2 float4 = 8 floats
        const float4* gsrc = reinterpret_cast<const float4*>(
            (mat ? kr : e) + (size_t)(r0 + row) * KDIM + seg * 8);
        float4 v0 = __ldcs(gsrc);
        float4 v1 = __ldcs(gsrc + 1);
        __half2 h0 = __halves2half2(__float2half_rn(v0.x), __float2half_rn(v0.y));
        __half2 h1 = __halves2half2(__float2half_rn(v0.z), __float2half_rn(v0.w));
        __half2 h2 = __halves2half2(__float2half_rn(v1.x), __float2half_rn(v1.y));
        __half2 h3 = __halves2half2(__float2half_rn(v1.z), __float2half_rn(v1.w));
        uint4 pk;
        pk.x = *reinterpret_cast<uint32_t*>(&h0);
        pk.y = *reinterpret_cast<uint32_t*>(&h1);
        pk.z = *reinterpret_cast<uint32_t*>(&h2);
        pk.w = *reinterpret_cast<uint32_t*>(&h3);
        *reinterpret_cast<uint4*>((mat ? sAK : sAE) + row * AW + seg * 8) = pk;
    }

    cp_wait_all();
    __syncthreads();

    // ---- MMA sweep: 8 k-steps ----
    const int warp_m = wid & 1;
    const int warp_n = wid >> 1;

    wmma::fragment<wmma::accumulator, 16, 16, 16, float> accE[2][2], accR[2][2];
#pragma unroll
    for (int tm = 0; tm < 2; ++tm)
#pragma unroll
        for (int tn = 0; tn < 2; ++tn) {
            wmma::fill_fragment(accE[tm][tn], 0.0f);
            wmma::fill_fragment(accR[tm][tn], 0.0f);
        }

#pragma unroll
    for (int ks = 0; ks < 8; ++ks) {
        wmma::fragment<wmma::matrix_a, 16, 16, 16, __half, wmma::row_major> a[2];
        wmma::fragment<wmma::matrix_b, 16, 16, 16, __half, wmma::row_major> b[2];
#pragma unroll
        for (int tm = 0; tm < 2; ++tm)
            wmma::load_matrix_sync(a[tm], sAE + (warp_m * 32 + tm * 16) * AW + ks * 16, AW);
#pragma unroll
        for (int tn = 0; tn < 2; ++tn)
            wmma::load_matrix_sync(b[tn], sBE + ks * 16 * BLD + warp_n * 32 + tn * 16, BLD);
#pragma unroll
        for (int tm = 0; tm < 2; ++tm)
#pragma unroll
            for (int tn = 0; tn < 2; ++tn)
                wmma::mma_sync(accE[tm][tn], a[tm], b[tn], accE[tm][tn]);
#pragma unroll
        for (int tm = 0; tm < 2; ++tm)
            wmma::load_matrix_sync(a[tm], sAK + (warp_m * 32 + tm * 16) * AW + ks * 16, AW);
#pragma unroll
        for (int tn = 0; tn < 2; ++tn)
            wmma::load_matrix_sync(b[tn], sBR + ks * 16 * BLD + warp_n * 32 + tn * 16, BLD);
#pragma unroll
        for (int tm = 0; tm < 2; ++tm)
#pragma unroll
            for (int tn = 0; tn < 2; ++tn)
                wmma::mma_sync(accR[tm][tn], a[tm], b[tn], accR[tm][tn]);
    }

    // ---- epilogue: stage projections into dead A region ----
    __syncthreads();
#pragma unroll
    for (int tm = 0; tm < 2; ++tm)
#pragma unroll
        for (int tn = 0; tn < 2; ++tn) {
            const int po = (warp_m * 32 + tm * 16) * PLD + warp_n * 32 + tn * 16;
            wmma::store_matrix_sync(projR + po, accR[tm][tn], PLD, wmma::mem_row_major);
            wmma::store_matrix_sync(projE + po, accE[tm][tn], PLD, wmma::mem_row_major);
        }
    __syncthreads();

    const int erow    = tid & 63;
    const int quarter = tid >> 6;
    const int cc      = quarter * 32;

    const int gedge = r0 + erow;
    const int sn  = sidx[erow];
    const int dn  = sidx[BM + erow];
    const int pos = sidx[2 * BM + erow];

    float s0 = 0.f, s1 = 0.f;
    float* oe = out_e + (size_t)gedge * CD + cc;
#pragma unroll
    for (int q = 0; q < 8; ++q) {
        float4 rv  = *reinterpret_cast<const float4*>(projR + erow * PLD + cc + q * 4);
        float4 rbv = *reinterpret_cast<const float4*>(Rb + cc + q * 4);
        float4 ev  = *reinterpret_cast<const float4*>(projE + erow * PLD + cc + q * 4);
        float4 ebv = *reinterpret_cast<const float4*>(Eb + cc + q * 4);
        float4 kv  = __ldg(reinterpret_cast<const float4*>(g_Kh + (size_t)sn * CD + cc + q * 4));
        float4 qv  = __ldg(reinterpret_cast<const float4*>(g_Qh + (size_t)dn * CD + cc + q * 4));
        const float pr[4] = {rv.x + rbv.x, rv.y + rbv.y, rv.z + rbv.z, rv.w + rbv.w};
        const float pe[4] = {ev.x + ebv.x, ev.y + ebv.y, ev.z + ebv.z, ev.w + ebv.w};
        const float kk[4] = {kv.x, kv.y, kv.z, kv.w};
        const float qq[4] = {qv.x, qv.y, qv.z, qv.w};
        float sc[4];
#pragma unroll
        for (int j = 0; j < 4; ++j) {
            float t = fmaf(kk[j] * qq[j], 0.25f, pr[j]) * pe[j];
            sc[j] = t;
            if (q < 4) s0 += t; else s1 += t;
        }
        __stcs(reinterpret_cast<float4*>(oe + q * 4), make_float4(sc[0], sc[1], sc[2], sc[3]));
    }

    s0 = __expf(fminf(fmaxf(s0, -5.0f), 5.0f));
    s1 = __expf(fminf(fmaxf(s1, -5.0f), 5.0f));

    // store s in CSR order (contiguous for the gather kernel)
    *reinterpret_cast<float2*>(&g_s[(size_t)pos * NH + quarter * 2]) = make_float2(s0, s1);
}

// ================= gather kernel: one warp per node, contiguous s =================
__global__ __launch_bounds__(256) void gather_kernel(float* __restrict__ out_h)
{
    const int node = (blockIdx.x * 256 + threadIdx.x) >> 5;
    const int lane = threadIdx.x & 31;
    if (node >= NN) return;

    const int off0 = g_off[node];
    const int off1 = g_off[node + 1];
    const int head = lane >> 2;

    float4 acc = make_float4(0.f, 0.f, 0.f, 0.f);
    float zs = 0.f;

    int i = off0;
    for (; i + 2 <= off1; i += 2) {
        int   s0n = g_esrc[i];
        int   s1n = g_esrc[i + 1];
        float w0 = g_s[(size_t)i * NH + head];
        float w1 = g_s[(size_t)(i + 1) * NH + head];
        float4 v0 = __ldg(reinterpret_cast<const float4*>(g_Vh + (size_t)s0n * CD + lane * 4));
        float4 v1 = __ldg(reinterpret_cast<const float4*>(g_Vh + (size_t)s1n * CD + lane * 4));
        acc.x = fmaf(w0, v0.x, acc.x); acc.y = fmaf(w0, v0.y, acc.y);
        acc.z = fmaf(w0, v0.z, acc.z); acc.w = fmaf(w0, v0.w, acc.w);
        acc.x = fmaf(w1, v1.x, acc.x); acc.y = fmaf(w1, v1.y, acc.y);
        acc.z = fmaf(w1, v1.z, acc.z); acc.w = fmaf(w1, v1.w, acc.w);
        zs += w0 + w1;
    }
    if (i < off1) {
        int   sn = g_esrc[i];
        float w = g_s[(size_t)i * NH + head];
        float4 v = __ldg(reinterpret_cast<const float4*>(g_Vh + (size_t)sn * CD + lane * 4));
        acc.x = fmaf(w, v.x, acc.x); acc.y = fmaf(w, v.y, acc.y);
        acc.z = fmaf(w, v.z, acc.z); acc.w = fmaf(w, v.w, acc.w);
        zs += w;
    }

    float inv = 1.0f / (zs + 1e-6f);
    acc.x *= inv; acc.y *= inv; acc.z *= inv; acc.w *= inv;
    *reinterpret_cast<float4*>(out_h + (size_t)node * CD + lane * 4) = acc;
}

// ================= node kernel: bf16 3-split (unchanged) =================
#define NSM_AH   0
#define NSM_AL   (NSM_AH + 64 * AFULL * 2)
#define NSM_BH   (NSM_AL + 64 * AFULL * 2)
#define NSM_BL   (NSM_BH + KDIM * BLD * 2)
#define NSM_TOTAL (NSM_BL + KDIM * BLD * 2)   // 104448

__global__ __launch_bounds__(256, 2) void node_proj_qkv_kernel(
    const float* __restrict__ h,
    const float* __restrict__ Qb, const float* __restrict__ Kb, const float* __restrict__ Vb,
    float* __restrict__ outQ, float* __restrict__ outK, float* __restrict__ outV)
{
    extern __shared__ char smem[];
    __nv_bfloat16* sAH = reinterpret_cast<__nv_bfloat16*>(smem + NSM_AH);
    __nv_bfloat16* sAL = reinterpret_cast<__nv_bfloat16*>(smem + NSM_AL);
    __nv_bfloat16* sBH = reinterpret_cast<__nv_bfloat16*>(smem + NSM_BH);
    __nv_bfloat16* sBL = reinterpret_cast<__nv_bfloat16*>(smem + NSM_BL);
    float*        proj = reinterpret_cast<float*>(smem + NSM_BH);

    const int tid = threadIdx.x;
    const int wid = tid >> 5;
    const int r0  = blockIdx.x * 64;

    for (int i = tid; i < 64 * 32; i += 256) {
        int row = i >> 5, kq = i & 31;
        float4 v = make_float4(0.f, 0.f, 0.f, 0.f);
        if (r0 + row < NN)
            v = reinterpret_cast<const float4*>(h + (size_t)(r0 + row) * KDIM)[kq];
        const float a[4] = {v.x, v.y, v.z, v.w};
        int off = row * AFULL + kq * 4;
#pragma unroll
        for (int j = 0; j < 4; ++j) {
            __nv_bfloat16 hh, ll;
            cvt_split_bf(a[j], hh, ll);
            sAH[off + j] = hh; sAL[off + j] = ll;
        }
    }

    const float* Bs[3] = {Qb, Kb, Vb};
    float* Os[3] = {outQ, outK, outV};

    const int warp_m = wid & 1;
    const int warp_n = wid >> 1;

    for (int m = 0; m < 3; ++m) {
        __syncthreads();
        for (int i = tid; i < KDIM * (CD / 8); i += 256) {
            int krow = i >> 4, q = i & 15;
            size_t goff = (size_t)krow * CD + q * 8;
            int soff = krow * BLD + q * 8;
            *reinterpret_cast<uint4*>(sBH + soff) = *reinterpret_cast<const uint4*>(&g_Wn_h[m][goff]);
            *reinterpret_cast<uint4*>(sBL + soff) = *reinterpret_cast<const uint4*>(&g_Wn_l[m][goff]);
        }
        __syncthreads();

        wmma::fragment<wmma::accumulator, 16, 16, 16, float> acc[2][2];
#pragma unroll
        for (int tm = 0; tm < 2; ++tm)
#pragma unroll
            for (int tn = 0; tn < 2; ++tn) wmma::fill_fragment(acc[tm][tn], 0.0f);

#pragma unroll
        for (int ks = 0; ks < KDIM / 16; ++ks) {
            wmma::fragment<wmma::matrix_a, 16, 16, 16, __nv_bfloat16, wmma::row_major> aH[2], aL[2];
            wmma::fragment<wmma::matrix_b, 16, 16, 16, __nv_bfloat16, wmma::row_major> bH[2], bL[2];
#pragma unroll
            for (int tm = 0; tm < 2; ++tm) {
                const int ar = warp_m * 32 + tm * 16;
                wmma::load_matrix_sync(aH[tm], sAH + ar * AFULL + ks * 16, AFULL);
                wmma::load_matrix_sync(aL[tm], sAL + ar * AFULL + ks * 16, AFULL);
            }
#pragma unroll
            for (int tn = 0; tn < 2; ++tn) {
                const int bc = warp_n * 32 + tn * 16;
                wmma::load_matrix_sync(bH[tn], sBH + ks * 16 * BLD + bc, BLD);
                wmma::load_matrix_sync(bL[tn], sBL + ks * 16 * BLD + bc, BLD);
            }
#pragma unroll
            for (int tm = 0; tm < 2; ++tm)
#pragma unroll
                for (int tn = 0; tn < 2; ++tn) {
                    wmma::mma_sync(acc[tm][tn], aH[tm], bH[tn], acc[tm][tn]);
                    wmma::mma_sync(acc[tm][tn], aH[tm], bL[tn], acc[tm][tn]);
                    wmma::mma_sync(acc[tm][tn], aL[tm], bH[tn], acc[tm][tn]);
                }
        }

        __syncthreads();
#pragma unroll
        for (int tm = 0; tm < 2; ++tm)
#pragma unroll
            for (int tn = 0; tn < 2; ++tn)
                wmma::store_matrix_sync(proj + (warp_m * 32 + tm * 16) * PLD + warp_n * 32 + tn * 16,
                                        acc[tm][tn], PLD, wmma::mem_row_major);
        __syncthreads();

        const int row = tid >> 2;
        const int cq  = (tid & 3) * 32;
        if (r0 + row < NN) {
            float* out = Os[m] + (size_t)(r0 + row) * CD + cq;
#pragma unroll
            for (int q = 0; q < 8; ++q) {
                float4 v  = *reinterpret_cast<const float4*>(proj + row * PLD + cq + q * 4);
                float4 bv = *reinterpret_cast<const float4*>(Bs[m] + cq + q * 4);
                reinterpret_cast<float4*>(out + q * 4)[0] =
                    make_float4(v.x + bv.x, v.y + bv.y, v.z + bv.z, v.w + bv.w);
            }
        }
    }
}

// ---------------- launch ----------------
extern "C" void kernel_launch(void* const* d_in, const int* in_sizes, int n_in,
                              void* d_out, int out_size)
{
    const float* h   = (const float*)d_in[0];
    const float* e   = (const float*)d_in[1];
    const float* kr  = (const float*)d_in[2];
    const int*   src = (const int*)  d_in[3];
    const int*   dst = (const int*)  d_in[4];
    const float* Qw  = (const float*)d_in[5];
    const float* Qb  = (const float*)d_in[6];
    const float* Kw  = (const float*)d_in[7];
    const float* Kb  = (const float*)d_in[8];
    const float* Vw  = (const float*)d_in[9];
    const float* Vb  = (const float*)d_in[10];
    const float* Ew  = (const float*)d_in[11];
    const float* Eb  = (const float*)d_in[12];
    const float* Rw  = (const float*)d_in[13];
    const float* Rb  = (const float*)d_in[14];

    float* out_h = (float*)d_out;
    float* out_e = (float*)d_out + (size_t)NN * CD;

    cudaFuncSetAttribute(node_proj_qkv_kernel, cudaFuncAttributeMaxDynamicSharedMemorySize, NSM_TOTAL);
    cudaFuncSetAttribute(edge_kernel,          cudaFuncAttributeMaxDynamicSharedMemorySize, ESM_TOTAL);

    void* cp = nullptr;
    cudaGetSymbolAddress(&cp, g_cnt);
    cudaMemsetAsync(cp, 0, NN * sizeof(int));

    void *qp, *kp, *vp;
    cudaGetSymbolAddress(&qp, g_Qh);
    cudaGetSymbolAddress(&kp, g_Kh);
    cudaGetSymbolAddress(&vp, g_Vh);

    convert_weights_kernel<<<(KDIM * CD + 255) / 256, 256>>>(Ew, Rw, Qw, Kw, Vw);

    hist_kernel<<<(EE + 255) / 256, 256>>>(dst);
    scan_kernel<<<1, 1024>>>();
    fill_kernel<<<(EE + 255) / 256, 256>>>(src, dst);

    const int nodeBlocks = (NN + 63) / 64;  // 782
    node_proj_qkv_kernel<<<nodeBlocks, 256, NSM_TOTAL>>>(
        h, Qb, Kb, Vb, (float*)qp, (float*)kp, (float*)vp);

    edge_kernel<<<EE / BM, 256, ESM_TOTAL>>>(e, kr, src, dst, Eb, Rb, out_e);

    gather_kernel<<<(NN * 32 + 255) / 256, 256>>>(out_h);
}

// round 15
// speedup vs baseline: 1.2261x; 1.2261x over previous
#include <cuda_runtime.h>
#include <cuda_bf16.h>
#include <cuda_fp16.h>
#include <mma.h>
#include <math.h>
#include <stdint.h>

using namespace nvcuda;

#define NN 50000
#define EE 800000
#define KDIM 128
#define CD 128
#define NH 8

#define BM 64        // edges per block (edge kernel)
#define CHK 32       // K chunk
#define KCH (KDIM / CHK)
#define ALD 40       // A smem leading dim (half)
#define AFULL 136    // A smem leading dim full-K (bf16, node)
#define BLD 136      // B smem leading dim (16-bit elems)
#define PLD 132      // proj smem leading dim (floats)

// ---------------- device scratch ----------------
__device__ float g_Qh[(size_t)NN * CD];
__device__ float g_Kh[(size_t)NN * CD];
__device__ float g_Vh[(size_t)NN * CD];
__device__ float g_s[(size_t)EE * NH];     // per-edge per-head weight, CSR order
__device__ int   g_cnt[NN];
__device__ int   g_off[NN + 1];
__device__ int   g_cur[NN];
__device__ int   g_esrc[EE];               // src sorted by dst
__device__ int   g_pos[EE];                // edge -> CSR slot
// edge weights: single fp16 (0=Ew 1=Rw)
__device__ __align__(16) __half g_We[2][KDIM * CD];
// node weights: bf16 hi/lo (0=Qw 1=Kw 2=Vw)
__device__ __align__(16) __nv_bfloat16 g_Wn_h[3][KDIM * CD];
__device__ __align__(16) __nv_bfloat16 g_Wn_l[3][KDIM * CD];

__device__ __forceinline__ void cvt_split_bf(float x, __nv_bfloat16& hi, __nv_bfloat16& lo) {
    hi = __float2bfloat16(x);
    lo = __float2bfloat16(x - __bfloat162float(hi));
}
__device__ __forceinline__ void cp16(uint32_t saddr, const void* gptr) {
    asm volatile("cp.async.cg.shared.global [%0], [%1], 16;"
                 :: "r"(saddr), "l"(gptr) : "memory");
}
__device__ __forceinline__ void cp_commit() {
    asm volatile("cp.async.commit_group;" ::: "memory");
}
__device__ __forceinline__ void cp_wait_all() {
    asm volatile("cp.async.wait_group 0;" ::: "memory");
}

// ---------------- weight conversion ----------------
__global__ __launch_bounds__(256) void convert_weights_kernel(
    const float* __restrict__ Ew, const float* __restrict__ Rw,
    const float* __restrict__ Qw, const float* __restrict__ Kw,
    const float* __restrict__ Vw)
{
    int i = blockIdx.x * 256 + threadIdx.x;
    if (i >= KDIM * CD) return;
    g_We[0][i] = __float2half_rn(Ew[i]);
    g_We[1][i] = __float2half_rn(Rw[i]);
    {
        __nv_bfloat16 h, l;
        cvt_split_bf(Qw[i], h, l); g_Wn_h[0][i] = h; g_Wn_l[0][i] = l;
        cvt_split_bf(Kw[i], h, l); g_Wn_h[1][i] = h; g_Wn_l[1][i] = l;
        cvt_split_bf(Vw[i], h, l); g_Wn_h[2][i] = h; g_Wn_l[2][i] = l;
    }
}

// ---------------- CSR build ----------------
__global__ __launch_bounds__(256) void hist_kernel(const int* __restrict__ dst)
{
    int e = blockIdx.x * 256 + threadIdx.x;
    if (e < EE) atomicAdd(&g_cnt[dst[e]], 1);
}

__global__ __launch_bounds__(1024) void scan_kernel()
{
    __shared__ int part[1024];
    const int t = threadIdx.x;
    const int CHUNK = (NN + 1023) / 1024;
    const int base = t * CHUNK;
    int sum = 0;
    for (int i = 0; i < CHUNK; ++i) {
        int idx = base + i;
        if (idx < NN) sum += g_cnt[idx];
    }
    part[t] = sum;
    __syncthreads();
    for (int d = 1; d < 1024; d <<= 1) {
        int v = (t >= d) ? part[t - d] : 0;
        __syncthreads();
        part[t] += v;
        __syncthreads();
    }
    int run = (t == 0) ? 0 : part[t - 1];
    for (int i = 0; i < CHUNK; ++i) {
        int idx = base + i;
        if (idx < NN) {
            g_off[idx] = run;
            g_cur[idx] = run;
            run += g_cnt[idx];
        }
    }
    if (t == 1023) g_off[NN] = run;
}

__global__ __launch_bounds__(256) void fill_kernel(
    const int* __restrict__ src, const int* __restrict__ dst)
{
    int e = blockIdx.x * 256 + threadIdx.x;
    if (e >= EE) return;
    int pos = atomicAdd(&g_cur[dst[e]], 1);
    g_esrc[pos] = src[e];
    g_pos[e] = pos;
}

// ================= edge kernel (R13 structure): fp16 A1xB1, double-buffered =================
#define ESM_SIDX  0                           // 3*64 ints = 768, pad to 1024
#define ESM_A     1024
#define ABUF_SZ   (2 * BM * ALD * 2)
#define ESM_B     (ESM_A + 2 * ABUF_SZ)
#define SBT       (CHK * BLD * 2)
#define BBUF_SZ   (2 * SBT)
#define ESM_PROJE (ESM_B + 2 * BBUF_SZ)
#define ESM_TOTAL (ESM_PROJE + BM * PLD * 4)  // 90112

__global__ __launch_bounds__(256, 2) void edge_kernel(
    const float* __restrict__ e,
    const float* __restrict__ kr,
    const int*  __restrict__ src,
    const int*  __restrict__ dst,
    const float* __restrict__ Eb,
    const float* __restrict__ Rb,
    float* __restrict__ out_e)
{
    extern __shared__ char smem[];
    int*   sidx  = reinterpret_cast<int*>(smem + ESM_SIDX);   // [src 64][dst 64][pos 64]
    float* projR = reinterpret_cast<float*>(smem + ESM_B);
    float* projE = reinterpret_cast<float*>(smem + ESM_PROJE);

    const int tid = threadIdx.x;
    const int wid = tid >> 5;
    const int r0  = blockIdx.x * BM;

    const int bkrow0 = tid >> 4;
    const int bq     = tid & 15;

    {
        uint32_t bdst = (uint32_t)__cvta_generic_to_shared(smem + ESM_B);
#pragma unroll
        for (int it = 0; it < 2; ++it) {
            int krow = bkrow0 + 16 * it;
            size_t goff = (size_t)krow * CD + bq * 8;
            uint32_t soff = (uint32_t)(krow * BLD + bq * 8) * 2;
            cp16(bdst + 0 * SBT + soff, &g_We[0][goff]);
            cp16(bdst + 1 * SBT + soff, &g_We[1][goff]);
        }
        cp_commit();
    }

    if (tid < BM) {
        sidx[tid]          = src[r0 + tid];
        sidx[BM + tid]     = dst[r0 + tid];
        sidx[2 * BM + tid] = g_pos[r0 + tid];
    }

    const int warp_m = wid & 1;
    const int warp_n = wid >> 1;
    const int arow0 = tid >> 3;
    const int aq    = tid & 7;

    wmma::fragment<wmma::accumulator, 16, 16, 16, float> accE[2][2], accR[2][2];
#pragma unroll
    for (int tm = 0; tm < 2; ++tm)
#pragma unroll
        for (int tn = 0; tn < 2; ++tn) {
            wmma::fill_fragment(accE[tm][tn], 0.0f);
            wmma::fill_fragment(accR[tm][tn], 0.0f);
        }

    float4 pve[2], pvk[2];
#pragma unroll
    for (int it = 0; it < 2; ++it) {
        const int row = arow0 + 32 * it;
        pve[it] = *reinterpret_cast<const float4*>(e  + (size_t)(r0 + row) * KDIM + aq * 4);
        pvk[it] = *reinterpret_cast<const float4*>(kr + (size_t)(r0 + row) * KDIM + aq * 4);
    }

    for (int ch = 0; ch < KCH; ++ch) {
        const int ab = ch & 1;
        __half* sAE = reinterpret_cast<__half*>(smem + ESM_A + ab * ABUF_SZ);
        __half* sAK = sAE + BM * ALD;

#pragma unroll
        for (int it = 0; it < 2; ++it) {
            const int row = arow0 + 32 * it;
            const int off = row * ALD + aq * 4;
            __half2* pe2 = reinterpret_cast<__half2*>(sAE + off);
            __half2* pk2 = reinterpret_cast<__half2*>(sAK + off);
            pe2[0] = __halves2half2(__float2half_rn(pve[it].x), __float2half_rn(pve[it].y));
            pe2[1] = __halves2half2(__float2half_rn(pve[it].z), __float2half_rn(pve[it].w));
            pk2[0] = __halves2half2(__float2half_rn(pvk[it].x), __float2half_rn(pvk[it].y));
            pk2[1] = __halves2half2(__float2half_rn(pvk[it].z), __float2half_rn(pvk[it].w));
        }
        if (ch < KCH - 1) {
            const int gk = (ch + 1) * CHK + aq * 4;
#pragma unroll
            for (int it = 0; it < 2; ++it) {
                const int row = arow0 + 32 * it;
                pve[it] = *reinterpret_cast<const float4*>(e  + (size_t)(r0 + row) * KDIM + gk);
                pvk[it] = *reinterpret_cast<const float4*>(kr + (size_t)(r0 + row) * KDIM + gk);
            }
        }

        cp_wait_all();
        __syncthreads();

        if (ch < KCH - 1) {
            uint32_t bdst = (uint32_t)__cvta_generic_to_shared(
                smem + ESM_B + ((ch + 1) & 1) * BBUF_SZ);
#pragma unroll
            for (int it = 0; it < 2; ++it) {
                int krow = bkrow0 + 16 * it;
                size_t goff = (size_t)((ch + 1) * CHK + krow) * CD + bq * 8;
                uint32_t soff = (uint32_t)(krow * BLD + bq * 8) * 2;
                cp16(bdst + 0 * SBT + soff, &g_We[0][goff]);
                cp16(bdst + 1 * SBT + soff, &g_We[1][goff]);
            }
            cp_commit();
        }

        __half* sB  = reinterpret_cast<__half*>(smem + ESM_B + ab * BBUF_SZ);
        __half* sBE = sB;
        __half* sBR = sB + SBT / 2;

#pragma unroll
        for (int ks = 0; ks < 2; ++ks) {
            wmma::fragment<wmma::matrix_a, 16, 16, 16, __half, wmma::row_major> a[2];
            wmma::fragment<wmma::matrix_b, 16, 16, 16, __half, wmma::row_major> b[2];
#pragma unroll
            for (int tm = 0; tm < 2; ++tm)
                wmma::load_matrix_sync(a[tm], sAE + (warp_m * 32 + tm * 16) * ALD + ks * 16, ALD);
#pragma unroll
            for (int tn = 0; tn < 2; ++tn)
                wmma::load_matrix_sync(b[tn], sBE + ks * 16 * BLD + warp_n * 32 + tn * 16, BLD);
#pragma unroll
            for (int tm = 0; tm < 2; ++tm)
#pragma unroll
                for (int tn = 0; tn < 2; ++tn)
                    wmma::mma_sync(accE[tm][tn], a[tm], b[tn], accE[tm][tn]);
#pragma unroll
            for (int tm = 0; tm < 2; ++tm)
                wmma::load_matrix_sync(a[tm], sAK + (warp_m * 32 + tm * 16) * ALD + ks * 16, ALD);
#pragma unroll
            for (int tn = 0; tn < 2; ++tn)
                wmma::load_matrix_sync(b[tn], sBR + ks * 16 * BLD + warp_n * 32 + tn * 16, BLD);
#pragma unroll
            for (int tm = 0; tm < 2; ++tm)
#pragma unroll
                for (int tn = 0; tn < 2; ++tn)
                    wmma::mma_sync(accR[tm][tn], a[tm], b[tn], accR[tm][tn]);
        }
    }

    __syncthreads();
#pragma unroll
    for (int tm = 0; tm < 2; ++tm)
#pragma unroll
        for (int tn = 0; tn < 2; ++tn) {
            const int po = (warp_m * 32 + tm * 16) * PLD + warp_n * 32 + tn * 16;
            wmma::store_matrix_sync(projR + po, accR[tm][tn], PLD, wmma::mem_row_major);
            wmma::store_matrix_sync(projE + po, accE[tm][tn], PLD, wmma::mem_row_major);
        }
    __syncthreads();

    const int erow    = tid & 63;
    const int quarter = tid >> 6;
    const int cc      = quarter * 32;

    const int gedge = r0 + erow;
    const int sn  = sidx[erow];
    const int dn  = sidx[BM + erow];
    const int pos = sidx[2 * BM + erow];

    float s0 = 0.f, s1 = 0.f;
    float* oe = out_e + (size_t)gedge * CD + cc;
#pragma unroll
    for (int q = 0; q < 8; ++q) {
        float4 rv  = *reinterpret_cast<const float4*>(projR + erow * PLD + cc + q * 4);
        float4 rbv = *reinterpret_cast<const float4*>(Rb + cc + q * 4);
        float4 ev  = *reinterpret_cast<const float4*>(projE + erow * PLD + cc + q * 4);
        float4 ebv = *reinterpret_cast<const float4*>(Eb + cc + q * 4);
        float4 kv  = *reinterpret_cast<const float4*>(g_Kh + (size_t)sn * CD + cc + q * 4);
        float4 qv  = *reinterpret_cast<const float4*>(g_Qh + (size_t)dn * CD + cc + q * 4);
        const float pr[4] = {rv.x + rbv.x, rv.y + rbv.y, rv.z + rbv.z, rv.w + rbv.w};
        const float pe[4] = {ev.x + ebv.x, ev.y + ebv.y, ev.z + ebv.z, ev.w + ebv.w};
        const float kk[4] = {kv.x, kv.y, kv.z, kv.w};
        const float qq[4] = {qv.x, qv.y, qv.z, qv.w};
        float sc[4];
#pragma unroll
        for (int j = 0; j < 4; ++j) {
            float t = fmaf(kk[j] * qq[j], 0.25f, pr[j]) * pe[j];
            sc[j] = t;
            if (q < 4) s0 += t; else s1 += t;
        }
        __stcs(reinterpret_cast<float4*>(oe + q * 4), make_float4(sc[0], sc[1], sc[2], sc[3]));
    }

    s0 = __expf(fminf(fmaxf(s0, -5.0f), 5.0f));
    s1 = __expf(fminf(fmaxf(s1, -5.0f), 5.0f));

    // store s in CSR order (contiguous for the gather kernel)
    *reinterpret_cast<float2*>(&g_s[(size_t)pos * NH + quarter * 2]) = make_float2(s0, s1);
}

// ================= gather kernel: one warp per node, contiguous s =================
__global__ __launch_bounds__(256) void gather_kernel(float* __restrict__ out_h)
{
    const int node = (blockIdx.x * 256 + threadIdx.x) >> 5;
    const int lane = threadIdx.x & 31;
    if (node >= NN) return;

    const int off0 = g_off[node];
    const int off1 = g_off[node + 1];
    const int head = lane >> 2;

    float4 acc = make_float4(0.f, 0.f, 0.f, 0.f);
    float zs = 0.f;

    int i = off0;
    for (; i + 2 <= off1; i += 2) {
        int   n0 = g_esrc[i];
        int   n1 = g_esrc[i + 1];
        float w0 = g_s[(size_t)i * NH + head];
        float w1 = g_s[(size_t)(i + 1) * NH + head];
        float4 v0 = __ldg(reinterpret_cast<const float4*>(g_Vh + (size_t)n0 * CD + lane * 4));
        float4 v1 = __ldg(reinterpret_cast<const float4*>(g_Vh + (size_t)n1 * CD + lane * 4));
        acc.x = fmaf(w0, v0.x, acc.x); acc.y = fmaf(w0, v0.y, acc.y);
        acc.z = fmaf(w0, v0.z, acc.z); acc.w = fmaf(w0, v0.w, acc.w);
        acc.x = fmaf(w1, v1.x, acc.x); acc.y = fmaf(w1, v1.y, acc.y);
        acc.z = fmaf(w1, v1.z, acc.z); acc.w = fmaf(w1, v1.w, acc.w);
        zs += w0 + w1;
    }
    if (i < off1) {
        int   n0 = g_esrc[i];
        float w = g_s[(size_t)i * NH + head];
        float4 v = __ldg(reinterpret_cast<const float4*>(g_Vh + (size_t)n0 * CD + lane * 4));
        acc.x = fmaf(w, v.x, acc.x); acc.y = fmaf(w, v.y, acc.y);
        acc.z = fmaf(w, v.z, acc.z); acc.w = fmaf(w, v.w, acc.w);
        zs += w;
    }

    float inv = 1.0f / (zs + 1e-6f);
    acc.x *= inv; acc.y *= inv; acc.z *= inv; acc.w *= inv;
    *reinterpret_cast<float4*>(out_h + (size_t)node * CD + lane * 4) = acc;
}

// ================= node kernel: bf16 3-split (unchanged) =================
#define NSM_AH   0
#define NSM_AL   (NSM_AH + 64 * AFULL * 2)
#define NSM_BH   (NSM_AL + 64 * AFULL * 2)
#define NSM_BL   (NSM_BH + KDIM * BLD * 2)
#define NSM_TOTAL (NSM_BL + KDIM * BLD * 2)   // 104448

__global__ __launch_bounds__(256, 2) void node_proj_qkv_kernel(
    const float* __restrict__ h,
    const float* __restrict__ Qb, const float* __restrict__ Kb, const float* __restrict__ Vb,
    float* __restrict__ outQ, float* __restrict__ outK, float* __restrict__ outV)
{
    extern __shared__ char smem[];
    __nv_bfloat16* sAH = reinterpret_cast<__nv_bfloat16*>(smem + NSM_AH);
    __nv_bfloat16* sAL = reinterpret_cast<__nv_bfloat16*>(smem + NSM_AL);
    __nv_bfloat16* sBH = reinterpret_cast<__nv_bfloat16*>(smem + NSM_BH);
    __nv_bfloat16* sBL = reinterpret_cast<__nv_bfloat16*>(smem + NSM_BL);
    float*        proj = reinterpret_cast<float*>(smem + NSM_BH);

    const int tid = threadIdx.x;
    const int wid = tid >> 5;
    const int r0  = blockIdx.x * 64;

    for (int i = tid; i < 64 * 32; i += 256) {
        int row = i >> 5, kq = i & 31;
        float4 v = make_float4(0.f, 0.f, 0.f, 0.f);
        if (r0 + row < NN)
            v = reinterpret_cast<const float4*>(h + (size_t)(r0 + row) * KDIM)[kq];
        const float a[4] = {v.x, v.y, v.z, v.w};
        int off = row * AFULL + kq * 4;
#pragma unroll
        for (int j = 0; j < 4; ++j) {
            __nv_bfloat16 hh, ll;
            cvt_split_bf(a[j], hh, ll);
            sAH[off + j] = hh; sAL[off + j] = ll;
        }
    }

    const float* Bs[3] = {Qb, Kb, Vb};
    float* Os[3] = {outQ, outK, outV};

    const int warp_m = wid & 1;
    const int warp_n = wid >> 1;

    for (int m = 0; m < 3; ++m) {
        __syncthreads();
        for (int i = tid; i < KDIM * (CD / 8); i += 256) {
            int krow = i >> 4, q = i & 15;
            size_t goff = (size_t)krow * CD + q * 8;
            int soff = krow * BLD + q * 8;
            *reinterpret_cast<uint4*>(sBH + soff) = *reinterpret_cast<const uint4*>(&g_Wn_h[m][goff]);
            *reinterpret_cast<uint4*>(sBL + soff) = *reinterpret_cast<const uint4*>(&g_Wn_l[m][goff]);
        }
        __syncthreads();

        wmma::fragment<wmma::accumulator, 16, 16, 16, float> acc[2][2];
#pragma unroll
        for (int tm = 0; tm < 2; ++tm)
#pragma unroll
            for (int tn = 0; tn < 2; ++tn) wmma::fill_fragment(acc[tm][tn], 0.0f);

#pragma unroll
        for (int ks = 0; ks < KDIM / 16; ++ks) {
            wmma::fragment<wmma::matrix_a, 16, 16, 16, __nv_bfloat16, wmma::row_major> aH[2], aL[2];
            wmma::fragment<wmma::matrix_b, 16, 16, 16, __nv_bfloat16, wmma::row_major> bH[2], bL[2];
#pragma unroll
            for (int tm = 0; tm < 2; ++tm) {
                const int ar = warp_m * 32 + tm * 16;
                wmma::load_matrix_sync(aH[tm], sAH + ar * AFULL + ks * 16, AFULL);
                wmma::load_matrix_sync(aL[tm], sAL + ar * AFULL + ks * 16, AFULL);
            }
#pragma unroll
            for (int tn = 0; tn < 2; ++tn) {
                const int bc = warp_n * 32 + tn * 16;
                wmma::load_matrix_sync(bH[tn], sBH + ks * 16 * BLD + bc, BLD);
                wmma::load_matrix_sync(bL[tn], sBL + ks * 16 * BLD + bc, BLD);
            }
#pragma unroll
            for (int tm = 0; tm < 2; ++tm)
#pragma unroll
                for (int tn = 0; tn < 2; ++tn) {
                    wmma::mma_sync(acc[tm][tn], aH[tm], bH[tn], acc[tm][tn]);
                    wmma::mma_sync(acc[tm][tn], aH[tm], bL[tn], acc[tm][tn]);
                    wmma::mma_sync(acc[tm][tn], aL[tm], bH[tn], acc[tm][tn]);
                }
        }

        __syncthreads();
#pragma unroll
        for (int tm = 0; tm < 2; ++tm)
#pragma unroll
            for (int tn = 0; tn < 2; ++tn)
                wmma::store_matrix_sync(proj + (warp_m * 32 + tm * 16) * PLD + warp_n * 32 + tn * 16,
                                        acc[tm][tn], PLD, wmma::mem_row_major);
        __syncthreads();

        const int row = tid >> 2;
        const int cq  = (tid & 3) * 32;
        if (r0 + row < NN) {
            float* out = Os[m] + (size_t)(r0 + row) * CD + cq;
#pragma unroll
            for (int q = 0; q < 8; ++q) {
                float4 v  = *reinterpret_cast<const float4*>(proj + row * PLD + cq + q * 4);
                float4 bv = *reinterpret_cast<const float4*>(Bs[m] + cq + q * 4);
                reinterpret_cast<float4*>(out + q * 4)[0] =
                    make_float4(v.x + bv.x, v.y + bv.y, v.z + bv.z, v.w + bv.w);
            }
        }
    }
}

// ---------------- launch ----------------
extern "C" void kernel_launch(void* const* d_in, const int* in_sizes, int n_in,
                              void* d_out, int out_size)
{
    const float* h   = (const float*)d_in[0];
    const float* e   = (const float*)d_in[1];
    const float* kr  = (const float*)d_in[2];
    const int*   src = (const int*)  d_in[3];
    const int*   dst = (const int*)  d_in[4];
    const float* Qw  = (const float*)d_in[5];
    const float* Qb  = (const float*)d_in[6];
    const float* Kw  = (const float*)d_in[7];
    const float* Kb  = (const float*)d_in[8];
    const float* Vw  = (const float*)d_in[9];
    const float* Vb  = (const float*)d_in[10];
    const float* Ew  = (const float*)d_in[11];
    const float* Eb  = (const float*)d_in[12];
    const float* Rw  = (const float*)d_in[13];
    const float* Rb  = (const float*)d_in[14];

    float* out_h = (float*)d_out;
    float* out_e = (float*)d_out + (size_t)NN * CD;

    cudaFuncSetAttribute(node_proj_qkv_kernel, cudaFuncAttributeMaxDynamicSharedMemorySize, NSM_TOTAL);
    cudaFuncSetAttribute(edge_kernel,          cudaFuncAttributeMaxDynamicSharedMemorySize, ESM_TOTAL);

    void* cp = nullptr;
    cudaGetSymbolAddress(&cp, g_cnt);
    cudaMemsetAsync(cp, 0, NN * sizeof(int));

    void *qp, *kp, *vp;
    cudaGetSymbolAddress(&qp, g_Qh);
    cudaGetSymbolAddress(&kp, g_Kh);
    cudaGetSymbolAddress(&vp, g_Vh);

    convert_weights_kernel<<<(KDIM * CD + 255) / 256, 256>>>(Ew, Rw, Qw, Kw, Vw);

    hist_kernel<<<(EE + 255) / 256, 256>>>(dst);
    scan_kernel<<<1, 1024>>>();
    fill_kernel<<<(EE + 255) / 256, 256>>>(src, dst);

    const int nodeBlocks = (NN + 63) / 64;  // 782
    node_proj_qkv_kernel<<<nodeBlocks, 256, NSM_TOTAL>>>(
        h, Qb, Kb, Vb, (float*)qp, (float*)kp, (float*)vp);

    edge_kernel<<<EE / BM, 256, ESM_TOTAL>>>(e, kr, src, dst, Eb, Rb, out_e);

    gather_kernel<<<(NN * 32 + 255) / 256, 256>>>(out_h);
}

// round 16
// speedup vs baseline: 1.3188x; 1.0756x over previous
#include <cuda_runtime.h>
#include <cuda_bf16.h>
#include <cuda_fp16.h>
#include <mma.h>
#include <math.h>
#include <stdint.h>

using namespace nvcuda;

#define NN 50000
#define EE 800000
#define KDIM 128
#define CD 128
#define NH 8

#define BM 64        // edges per block (edge kernel)
#define CHK 32       // K chunk
#define KCH (KDIM / CHK)
#define ALD 40       // A smem leading dim (half)
#define AFULL 136    // A smem leading dim full-K (bf16, node)
#define BLD 136      // B smem leading dim (16-bit elems)
#define PLD 132      // proj smem leading dim (floats)

// ---------------- device scratch ----------------
__device__ __half g_Qh[(size_t)NN * CD];   // fp16 node projections (Q, K)
__device__ __half g_Kh[(size_t)NN * CD];
__device__ float  g_Vh[(size_t)NN * CD];   // V stays fp32 (feeds out_h directly)
__device__ float  g_s[(size_t)EE * NH];    // per-edge per-head weight, CSR order
__device__ int    g_cnt[NN];
__device__ int    g_off[NN + 1];
__device__ int    g_cur[NN];
__device__ int    g_esrc[EE];              // src sorted by dst
__device__ int    g_pos[EE];               // edge -> CSR slot
// edge weights: single fp16 (0=Ew 1=Rw)
__device__ __align__(16) __half g_We[2][KDIM * CD];
// node weights: bf16 hi/lo (0=Qw 1=Kw 2=Vw)
__device__ __align__(16) __nv_bfloat16 g_Wn_h[3][KDIM * CD];
__device__ __align__(16) __nv_bfloat16 g_Wn_l[3][KDIM * CD];

__device__ __forceinline__ void cvt_split_bf(float x, __nv_bfloat16& hi, __nv_bfloat16& lo) {
    hi = __float2bfloat16(x);
    lo = __float2bfloat16(x - __bfloat162float(hi));
}
__device__ __forceinline__ void cp16(uint32_t saddr, const void* gptr) {
    asm volatile("cp.async.cg.shared.global [%0], [%1], 16;"
                 :: "r"(saddr), "l"(gptr) : "memory");
}
__device__ __forceinline__ void cp_commit() {
    asm volatile("cp.async.commit_group;" ::: "memory");
}
__device__ __forceinline__ void cp_wait_all() {
    asm volatile("cp.async.wait_group 0;" ::: "memory");
}

// ---------------- weight conversion ----------------
__global__ __launch_bounds__(256) void convert_weights_kernel(
    const float* __restrict__ Ew, const float* __restrict__ Rw,
    const float* __restrict__ Qw, const float* __restrict__ Kw,
    const float* __restrict__ Vw)
{
    int i = blockIdx.x * 256 + threadIdx.x;
    if (i >= KDIM * CD) return;
    g_We[0][i] = __float2half_rn(Ew[i]);
    g_We[1][i] = __float2half_rn(Rw[i]);
    {
        __nv_bfloat16 h, l;
        cvt_split_bf(Qw[i], h, l); g_Wn_h[0][i] = h; g_Wn_l[0][i] = l;
        cvt_split_bf(Kw[i], h, l); g_Wn_h[1][i] = h; g_Wn_l[1][i] = l;
        cvt_split_bf(Vw[i], h, l); g_Wn_h[2][i] = h; g_Wn_l[2][i] = l;
    }
}

// ---------------- CSR build ----------------
__global__ __launch_bounds__(256) void hist_kernel(const int* __restrict__ dst)
{
    int e = blockIdx.x * 256 + threadIdx.x;
    if (e < EE) atomicAdd(&g_cnt[dst[e]], 1);
}

__global__ __launch_bounds__(1024) void scan_kernel()
{
    __shared__ int part[1024];
    const int t = threadIdx.x;
    const int CHUNK = (NN + 1023) / 1024;
    const int base = t * CHUNK;
    int sum = 0;
    for (int i = 0; i < CHUNK; ++i) {
        int idx = base + i;
        if (idx < NN) sum += g_cnt[idx];
    }
    part[t] = sum;
    __syncthreads();
    for (int d = 1; d < 1024; d <<= 1) {
        int v = (t >= d) ? part[t - d] : 0;
        __syncthreads();
        part[t] += v;
        __syncthreads();
    }
    int run = (t == 0) ? 0 : part[t - 1];
    for (int i = 0; i < CHUNK; ++i) {
        int idx = base + i;
        if (idx < NN) {
            g_off[idx] = run;
            g_cur[idx] = run;
            run += g_cnt[idx];
        }
    }
    if (t == 1023) g_off[NN] = run;
}

__global__ __launch_bounds__(256) void fill_kernel(
    const int* __restrict__ src, const int* __restrict__ dst)
{
    int e = blockIdx.x * 256 + threadIdx.x;
    if (e >= EE) return;
    int pos = atomicAdd(&g_cur[dst[e]], 1);
    g_esrc[pos] = src[e];
    g_pos[e] = pos;
}

// ================= edge kernel (R13 structure): fp16 A1xB1, double-buffered =================
#define ESM_SIDX  0                           // 3*64 ints = 768, pad to 1024
#define ESM_A     1024
#define ABUF_SZ   (2 * BM * ALD * 2)
#define ESM_B     (ESM_A + 2 * ABUF_SZ)
#define SBT       (CHK * BLD * 2)
#define BBUF_SZ   (2 * SBT)
#define ESM_PROJE (ESM_B + 2 * BBUF_SZ)
#define ESM_TOTAL (ESM_PROJE + BM * PLD * 4)  // 90112

__global__ __launch_bounds__(256, 2) void edge_kernel(
    const float* __restrict__ e,
    const float* __restrict__ kr,
    const int*  __restrict__ src,
    const int*  __restrict__ dst,
    const float* __restrict__ Eb,
    const float* __restrict__ Rb,
    float* __restrict__ out_e)
{
    extern __shared__ char smem[];
    int*   sidx  = reinterpret_cast<int*>(smem + ESM_SIDX);   // [src 64][dst 64][pos 64]
    float* projR = reinterpret_cast<float*>(smem + ESM_B);
    float* projE = reinterpret_cast<float*>(smem + ESM_PROJE);

    const int tid = threadIdx.x;
    const int wid = tid >> 5;
    const int r0  = blockIdx.x * BM;

    const int bkrow0 = tid >> 4;
    const int bq     = tid & 15;

    {
        uint32_t bdst = (uint32_t)__cvta_generic_to_shared(smem + ESM_B);
#pragma unroll
        for (int it = 0; it < 2; ++it) {
            int krow = bkrow0 + 16 * it;
            size_t goff = (size_t)krow * CD + bq * 8;
            uint32_t soff = (uint32_t)(krow * BLD + bq * 8) * 2;
            cp16(bdst + 0 * SBT + soff, &g_We[0][goff]);
            cp16(bdst + 1 * SBT + soff, &g_We[1][goff]);
        }
        cp_commit();
    }

    if (tid < BM) {
        sidx[tid]          = src[r0 + tid];
        sidx[BM + tid]     = dst[r0 + tid];
        sidx[2 * BM + tid] = g_pos[r0 + tid];
    }

    const int warp_m = wid & 1;
    const int warp_n = wid >> 1;
    const int arow0 = tid >> 3;
    const int aq    = tid & 7;

    wmma::fragment<wmma::accumulator, 16, 16, 16, float> accE[2][2], accR[2][2];
#pragma unroll
    for (int tm = 0; tm < 2; ++tm)
#pragma unroll
        for (int tn = 0; tn < 2; ++tn) {
            wmma::fill_fragment(accE[tm][tn], 0.0f);
            wmma::fill_fragment(accR[tm][tn], 0.0f);
        }

    float4 pve[2], pvk[2];
#pragma unroll
    for (int it = 0; it < 2; ++it) {
        const int row = arow0 + 32 * it;
        pve[it] = *reinterpret_cast<const float4*>(e  + (size_t)(r0 + row) * KDIM + aq * 4);
        pvk[it] = *reinterpret_cast<const float4*>(kr + (size_t)(r0 + row) * KDIM + aq * 4);
    }

    for (int ch = 0; ch < KCH; ++ch) {
        const int ab = ch & 1;
        __half* sAE = reinterpret_cast<__half*>(smem + ESM_A + ab * ABUF_SZ);
        __half* sAK = sAE + BM * ALD;

#pragma unroll
        for (int it = 0; it < 2; ++it) {
            const int row = arow0 + 32 * it;
            const int off = row * ALD + aq * 4;
            __half2* pe2 = reinterpret_cast<__half2*>(sAE + off);
            __half2* pk2 = reinterpret_cast<__half2*>(sAK + off);
            pe2[0] = __halves2half2(__float2half_rn(pve[it].x), __float2half_rn(pve[it].y));
            pe2[1] = __halves2half2(__float2half_rn(pve[it].z), __float2half_rn(pve[it].w));
            pk2[0] = __halves2half2(__float2half_rn(pvk[it].x), __float2half_rn(pvk[it].y));
            pk2[1] = __halves2half2(__float2half_rn(pvk[it].z), __float2half_rn(pvk[it].w));
        }
        if (ch < KCH - 1) {
            const int gk = (ch + 1) * CHK + aq * 4;
#pragma unroll
            for (int it = 0; it < 2; ++it) {
                const int row = arow0 + 32 * it;
                pve[it] = *reinterpret_cast<const float4*>(e  + (size_t)(r0 + row) * KDIM + gk);
                pvk[it] = *reinterpret_cast<const float4*>(kr + (size_t)(r0 + row) * KDIM + gk);
            }
        }

        cp_wait_all();
        __syncthreads();

        if (ch < KCH - 1) {
            uint32_t bdst = (uint32_t)__cvta_generic_to_shared(
                smem + ESM_B + ((ch + 1) & 1) * BBUF_SZ);
#pragma unroll
            for (int it = 0; it < 2; ++it) {
                int krow = bkrow0 + 16 * it;
                size_t goff = (size_t)((ch + 1) * CHK + krow) * CD + bq * 8;
                uint32_t soff = (uint32_t)(krow * BLD + bq * 8) * 2;
                cp16(bdst + 0 * SBT + soff, &g_We[0][goff]);
                cp16(bdst + 1 * SBT + soff, &g_We[1][goff]);
            }
            cp_commit();
        }

        __half* sB  = reinterpret_cast<__half*>(smem + ESM_B + ab * BBUF_SZ);
        __half* sBE = sB;
        __half* sBR = sB + SBT / 2;

#pragma unroll
        for (int ks = 0; ks < 2; ++ks) {
            wmma::fragment<wmma::matrix_a, 16, 16, 16, __half, wmma::row_major> a[2];
            wmma::fragment<wmma::matrix_b, 16, 16, 16, __half, wmma::row_major> b[2];
#pragma unroll
            for (int tm = 0; tm < 2; ++tm)
                wmma::load_matrix_sync(a[tm], sAE + (warp_m * 32 + tm * 16) * ALD + ks * 16, ALD);
#pragma unroll
            for (int tn = 0; tn < 2; ++tn)
                wmma::load_matrix_sync(b[tn], sBE + ks * 16 * BLD + warp_n * 32 + tn * 16, BLD);
#pragma unroll
            for (int tm = 0; tm < 2; ++tm)
#pragma unroll
                for (int tn = 0; tn < 2; ++tn)
                    wmma::mma_sync(accE[tm][tn], a[tm], b[tn], accE[tm][tn]);
#pragma unroll
            for (int tm = 0; tm < 2; ++tm)
                wmma::load_matrix_sync(a[tm], sAK + (warp_m * 32 + tm * 16) * ALD + ks * 16, ALD);
#pragma unroll
            for (int tn = 0; tn < 2; ++tn)
                wmma::load_matrix_sync(b[tn], sBR + ks * 16 * BLD + warp_n * 32 + tn * 16, BLD);
#pragma unroll
            for (int tm = 0; tm < 2; ++tm)
#pragma unroll
                for (int tn = 0; tn < 2; ++tn)
                    wmma::mma_sync(accR[tm][tn], a[tm], b[tn], accR[tm][tn]);
        }
    }

    __syncthreads();
#pragma unroll
    for (int tm = 0; tm < 2; ++tm)
#pragma unroll
        for (int tn = 0; tn < 2; ++tn) {
            const int po = (warp_m * 32 + tm * 16) * PLD + warp_n * 32 + tn * 16;
            wmma::store_matrix_sync(projR + po, accR[tm][tn], PLD, wmma::mem_row_major);
            wmma::store_matrix_sync(projE + po, accE[tm][tn], PLD, wmma::mem_row_major);
        }
    __syncthreads();

    const int erow    = tid & 63;
    const int quarter = tid >> 6;
    const int cc      = quarter * 32;

    const int gedge = r0 + erow;
    const int sn  = sidx[erow];
    const int dn  = sidx[BM + erow];
    const int pos = sidx[2 * BM + erow];

    const __half* Kp = g_Kh + (size_t)sn * CD + cc;
    const __half* Qp = g_Qh + (size_t)dn * CD + cc;

    float s0 = 0.f, s1 = 0.f;
    float* oe = out_e + (size_t)gedge * CD + cc;
#pragma unroll
    for (int q = 0; q < 8; ++q) {
        float4 rv  = *reinterpret_cast<const float4*>(projR + erow * PLD + cc + q * 4);
        float4 rbv = *reinterpret_cast<const float4*>(Rb + cc + q * 4);
        float4 ev  = *reinterpret_cast<const float4*>(projE + erow * PLD + cc + q * 4);
        float4 ebv = *reinterpret_cast<const float4*>(Eb + cc + q * 4);
        // fp16 K/Q: 4 halves each = 8 bytes
        uint2 ku = *reinterpret_cast<const uint2*>(Kp + q * 4);
        uint2 qu = *reinterpret_cast<const uint2*>(Qp + q * 4);
        float2 k01 = __half22float2(*reinterpret_cast<const __half2*>(&ku.x));
        float2 k23 = __half22float2(*reinterpret_cast<const __half2*>(&ku.y));
        float2 q01 = __half22float2(*reinterpret_cast<const __half2*>(&qu.x));
        float2 q23 = __half22float2(*reinterpret_cast<const __half2*>(&qu.y));
        const float pr[4] = {rv.x + rbv.x, rv.y + rbv.y, rv.z + rbv.z, rv.w + rbv.w};
        const float pe[4] = {ev.x + ebv.x, ev.y + ebv.y, ev.z + ebv.z, ev.w + ebv.w};
        const float kk[4] = {k01.x, k01.y, k23.x, k23.y};
        const float qq[4] = {q01.x, q01.y, q23.x, q23.y};
        float sc[4];
#pragma unroll
        for (int j = 0; j < 4; ++j) {
            float t = fmaf(kk[j] * qq[j], 0.25f, pr[j]) * pe[j];
            sc[j] = t;
            if (q < 4) s0 += t; else s1 += t;
        }
        __stcs(reinterpret_cast<float4*>(oe + q * 4), make_float4(sc[0], sc[1], sc[2], sc[3]));
    }

    s0 = __expf(fminf(fmaxf(s0, -5.0f), 5.0f));
    s1 = __expf(fminf(fmaxf(s1, -5.0f), 5.0f));

    *reinterpret_cast<float2*>(&g_s[(size_t)pos * NH + quarter * 2]) = make_float2(s0, s1);
}

// ================= gather kernel: one warp per node =================
__global__ __launch_bounds__(256) void gather_kernel(float* __restrict__ out_h)
{
    const int node = (blockIdx.x * 256 + threadIdx.x) >> 5;
    const int lane = threadIdx.x & 31;
    if (node >= NN) return;

    const int off0 = g_off[node];
    const int off1 = g_off[node + 1];
    const int head = lane >> 2;

    float4 acc = make_float4(0.f, 0.f, 0.f, 0.f);
    float zs = 0.f;

    int i = off0;
    for (; i + 2 <= off1; i += 2) {
        int   n0 = g_esrc[i];
        int   n1 = g_esrc[i + 1];
        float w0 = g_s[(size_t)i * NH + head];
        float w1 = g_s[(size_t)(i + 1) * NH + head];
        float4 v0 = __ldg(reinterpret_cast<const float4*>(g_Vh + (size_t)n0 * CD + lane * 4));
        float4 v1 = __ldg(reinterpret_cast<const float4*>(g_Vh + (size_t)n1 * CD + lane * 4));
        acc.x = fmaf(w0, v0.x, acc.x); acc.y = fmaf(w0, v0.y, acc.y);
        acc.z = fmaf(w0, v0.z, acc.z); acc.w = fmaf(w0, v0.w, acc.w);
        acc.x = fmaf(w1, v1.x, acc.x); acc.y = fmaf(w1, v1.y, acc.y);
        acc.z = fmaf(w1, v1.z, acc.z); acc.w = fmaf(w1, v1.w, acc.w);
        zs += w0 + w1;
    }
    if (i < off1) {
        int   n0 = g_esrc[i];
        float w = g_s[(size_t)i * NH + head];
        float4 v = __ldg(reinterpret_cast<const float4*>(g_Vh + (size_t)n0 * CD + lane * 4));
        acc.x = fmaf(w, v.x, acc.x); acc.y = fmaf(w, v.y, acc.y);
        acc.z = fmaf(w, v.z, acc.z); acc.w = fmaf(w, v.w, acc.w);
        zs += w;
    }

    float inv = 1.0f / (zs + 1e-6f);
    acc.x *= inv; acc.y *= inv; acc.z *= inv; acc.w *= inv;
    *reinterpret_cast<float4*>(out_h + (size_t)node * CD + lane * 4) = acc;
}

// ================= node kernel: bf16 3-split; Q,K stored fp16, V fp32 =================
#define NSM_AH   0
#define NSM_AL   (NSM_AH + 64 * AFULL * 2)
#define NSM_BH   (NSM_AL + 64 * AFULL * 2)
#define NSM_BL   (NSM_BH + KDIM * BLD * 2)
#define NSM_TOTAL (NSM_BL + KDIM * BLD * 2)   // 104448

__global__ __launch_bounds__(256, 2) void node_proj_qkv_kernel(
    const float* __restrict__ h,
    const float* __restrict__ Qb, const float* __restrict__ Kb, const float* __restrict__ Vb,
    __half* __restrict__ outQ, __half* __restrict__ outK, float* __restrict__ outV)
{
    extern __shared__ char smem[];
    __nv_bfloat16* sAH = reinterpret_cast<__nv_bfloat16*>(smem + NSM_AH);
    __nv_bfloat16* sAL = reinterpret_cast<__nv_bfloat16*>(smem + NSM_AL);
    __nv_bfloat16* sBH = reinterpret_cast<__nv_bfloat16*>(smem + NSM_BH);
    __nv_bfloat16* sBL = reinterpret_cast<__nv_bfloat16*>(smem + NSM_BL);
    float*        proj = reinterpret_cast<float*>(smem + NSM_BH);

    const int tid = threadIdx.x;
    const int wid = tid >> 5;
    const int r0  = blockIdx.x * 64;

    for (int i = tid; i < 64 * 32; i += 256) {
        int row = i >> 5, kq = i & 31;
        float4 v = make_float4(0.f, 0.f, 0.f, 0.f);
        if (r0 + row < NN)
            v = reinterpret_cast<const float4*>(h + (size_t)(r0 + row) * KDIM)[kq];
        const float a[4] = {v.x, v.y, v.z, v.w};
        int off = row * AFULL + kq * 4;
#pragma unroll
        for (int j = 0; j < 4; ++j) {
            __nv_bfloat16 hh, ll;
            cvt_split_bf(a[j], hh, ll);
            sAH[off + j] = hh; sAL[off + j] = ll;
        }
    }

    const float* Bs[3] = {Qb, Kb, Vb};

    const int warp_m = wid & 1;
    const int warp_n = wid >> 1;

    for (int m = 0; m < 3; ++m) {
        __syncthreads();
        for (int i = tid; i < KDIM * (CD / 8); i += 256) {
            int krow = i >> 4, q = i & 15;
            size_t goff = (size_t)krow * CD + q * 8;
            int soff = krow * BLD + q * 8;
            *reinterpret_cast<uint4*>(sBH + soff) = *reinterpret_cast<const uint4*>(&g_Wn_h[m][goff]);
            *reinterpret_cast<uint4*>(sBL + soff) = *reinterpret_cast<const uint4*>(&g_Wn_l[m][goff]);
        }
        __syncthreads();

        wmma::fragment<wmma::accumulator, 16, 16, 16, float> acc[2][2];
#pragma unroll
        for (int tm = 0; tm < 2; ++tm)
#pragma unroll
            for (int tn = 0; tn < 2; ++tn) wmma::fill_fragment(acc[tm][tn], 0.0f);

#pragma unroll
        for (int ks = 0; ks < KDIM / 16; ++ks) {
            wmma::fragment<wmma::matrix_a, 16, 16, 16, __nv_bfloat16, wmma::row_major> aH[2], aL[2];
            wmma::fragment<wmma::matrix_b, 16, 16, 16, __nv_bfloat16, wmma::row_major> bH[2], bL[2];
#pragma unroll
            for (int tm = 0; tm < 2; ++tm) {
                const int ar = warp_m * 32 + tm * 16;
                wmma::load_matrix_sync(aH[tm], sAH + ar * AFULL + ks * 16, AFULL);
                wmma::load_matrix_sync(aL[tm], sAL + ar * AFULL + ks * 16, AFULL);
            }
#pragma unroll
            for (int tn = 0; tn < 2; ++tn) {
                const int bc = warp_n * 32 + tn * 16;
                wmma::load_matrix_sync(bH[tn], sBH + ks * 16 * BLD + bc, BLD);
                wmma::load_matrix_sync(bL[tn], sBL + ks * 16 * BLD + bc, BLD);
            }
#pragma unroll
            for (int tm = 0; tm < 2; ++tm)
#pragma unroll
                for (int tn = 0; tn < 2; ++tn) {
                    wmma::mma_sync(acc[tm][tn], aH[tm], bH[tn], acc[tm][tn]);
                    wmma::mma_sync(acc[tm][tn], aH[tm], bL[tn], acc[tm][tn]);
                    wmma::mma_sync(acc[tm][tn], aL[tm], bH[tn], acc[tm][tn]);
                }
        }

        __syncthreads();
#pragma unroll
        for (int tm = 0; tm < 2; ++tm)
#pragma unroll
            for (int tn = 0; tn < 2; ++tn)
                wmma::store_matrix_sync(proj + (warp_m * 32 + tm * 16) * PLD + warp_n * 32 + tn * 16,
                                        acc[tm][tn], PLD, wmma::mem_row_major);
        __syncthreads();

        const int row = tid >> 2;
        const int cq  = (tid & 3) * 32;
        if (r0 + row < NN) {
            if (m < 2) {
                __half* out = (m == 0 ? outQ : outK) + (size_t)(r0 + row) * CD + cq;
#pragma unroll
                for (int q = 0; q < 8; ++q) {
                    float4 v  = *reinterpret_cast<const float4*>(proj + row * PLD + cq + q * 4);
                    float4 bv = *reinterpret_cast<const float4*>(Bs[m] + cq + q * 4);
                    __half2 h01 = __floats2half2_rn(v.x + bv.x, v.y + bv.y);
                    __half2 h23 = __floats2half2_rn(v.z + bv.z, v.w + bv.w);
                    uint2 pk;
                    pk.x = *reinterpret_cast<uint32_t*>(&h01);
                    pk.y = *reinterpret_cast<uint32_t*>(&h23);
                    *reinterpret_cast<uint2*>(out + q * 4) = pk;
                }
            } else {
                float* out = outV + (size_t)(r0 + row) * CD + cq;
#pragma unroll
                for (int q = 0; q < 8; ++q) {
                    float4 v  = *reinterpret_cast<const float4*>(proj + row * PLD + cq + q * 4);
                    float4 bv = *reinterpret_cast<const float4*>(Bs[m] + cq + q * 4);
                    reinterpret_cast<float4*>(out + q * 4)[0] =
                        make_float4(v.x + bv.x, v.y + bv.y, v.z + bv.z, v.w + bv.w);
                }
            }
        }
    }
}

// ---------------- launch ----------------
extern "C" void kernel_launch(void* const* d_in, const int* in_sizes, int n_in,
                              void* d_out, int out_size)
{
    const float* h   = (const float*)d_in[0];
    const float* e   = (const float*)d_in[1];
    const float* kr  = (const float*)d_in[2];
    const int*   src = (const int*)  d_in[3];
    const int*   dst = (const int*)  d_in[4];
    const float* Qw  = (const float*)d_in[5];
    const float* Qb  = (const float*)d_in[6];
    const float* Kw  = (const float*)d_in[7];
    const float* Kb  = (const float*)d_in[8];
    const float* Vw  = (const float*)d_in[9];
    const float* Vb  = (const float*)d_in[10];
    const float* Ew  = (const float*)d_in[11];
    const float* Eb  = (const float*)d_in[12];
    const float* Rw  = (const float*)d_in[13];
    const float* Rb  = (const float*)d_in[14];

    float* out_h = (float*)d_out;
    float* out_e = (float*)d_out + (size_t)NN * CD;

    cudaFuncSetAttribute(node_proj_qkv_kernel, cudaFuncAttributeMaxDynamicSharedMemorySize, NSM_TOTAL);
    cudaFuncSetAttribute(edge_kernel,          cudaFuncAttributeMaxDynamicSharedMemorySize, ESM_TOTAL);

    void* cp = nullptr;
    cudaGetSymbolAddress(&cp, g_cnt);
    cudaMemsetAsync(cp, 0, NN * sizeof(int));

    void *qp, *kp, *vp;
    cudaGetSymbolAddress(&qp, g_Qh);
    cudaGetSymbolAddress(&kp, g_Kh);
    cudaGetSymbolAddress(&vp, g_Vh);

    convert_weights_kernel<<<(KDIM * CD + 255) / 256, 256>>>(Ew, Rw, Qw, Kw, Vw);

    hist_kernel<<<(EE + 255) / 256, 256>>>(dst);
    scan_kernel<<<1, 1024>>>();
    fill_kernel<<<(EE + 255) / 256, 256>>>(src, dst);

    const int nodeBlocks = (NN + 63) / 64;  // 782
    node_proj_qkv_kernel<<<nodeBlocks, 256, NSM_TOTAL>>>(
        h, Qb, Kb, Vb, (__half*)qp, (__half*)kp, (float*)vp);

    edge_kernel<<<EE / BM, 256, ESM_TOTAL>>>(e, kr, src, dst, Eb, Rb, out_e);

    gather_kernel<<<(NN * 32 + 255) / 256, 256>>>(out_h);
}

// round 17
// speedup vs baseline: 1.4026x; 1.0636x over previous
#include <cuda_runtime.h>
#include <cuda_fp16.h>
#include <mma.h>
#include <math.h>
#include <stdint.h>

using namespace nvcuda;

#define NN 50000
#define EE 800000
#define KDIM 128
#define CD 128
#define NH 8

#define BM 64        // edges per block (edge kernel)
#define CHK 32       // K chunk
#define KCH (KDIM / CHK)
#define ALD 40       // A smem leading dim (half)
#define AFULL 136    // node A leading dim (half)
#define BLD 136      // B smem leading dim (16-bit elems)
#define PLD 132      // proj smem leading dim (floats)

// ---------------- device scratch ----------------
__device__ __half g_Qh[(size_t)NN * CD];   // fp16 node projections
__device__ __half g_Kh[(size_t)NN * CD];
__device__ __half g_Vh[(size_t)NN * CD];
__device__ float  g_s[(size_t)EE * NH];    // per-edge per-head weight, CSR order
__device__ int    g_cnt[NN];
__device__ int    g_off[NN + 1];
__device__ int    g_cur[NN];
__device__ int    g_esrc[EE];              // src sorted by dst
__device__ int    g_pos[EE];               // edge -> CSR slot
// fp16 weights: 0=Ew 1=Rw 2=Qw 3=Kw 4=Vw
__device__ __align__(16) __half g_We[5][KDIM * CD];

__device__ __forceinline__ void cp16(uint32_t saddr, const void* gptr) {
    asm volatile("cp.async.cg.shared.global [%0], [%1], 16;"
                 :: "r"(saddr), "l"(gptr) : "memory");
}
__device__ __forceinline__ void cp_commit() {
    asm volatile("cp.async.commit_group;" ::: "memory");
}
__device__ __forceinline__ void cp_wait_all() {
    asm volatile("cp.async.wait_group 0;" ::: "memory");
}

// ---------------- weight conversion ----------------
__global__ __launch_bounds__(256) void convert_weights_kernel(
    const float* __restrict__ Ew, const float* __restrict__ Rw,
    const float* __restrict__ Qw, const float* __restrict__ Kw,
    const float* __restrict__ Vw)
{
    int i = blockIdx.x * 256 + threadIdx.x;
    if (i >= KDIM * CD) return;
    g_We[0][i] = __float2half_rn(Ew[i]);
    g_We[1][i] = __float2half_rn(Rw[i]);
    g_We[2][i] = __float2half_rn(Qw[i]);
    g_We[3][i] = __float2half_rn(Kw[i]);
    g_We[4][i] = __float2half_rn(Vw[i]);
}

// ---------------- CSR build ----------------
__global__ __launch_bounds__(256) void hist_kernel(const int* __restrict__ dst)
{
    int e = blockIdx.x * 256 + threadIdx.x;
    if (e < EE) atomicAdd(&g_cnt[dst[e]], 1);
}

__global__ __launch_bounds__(1024) void scan_kernel()
{
    __shared__ int part[1024];
    const int t = threadIdx.x;
    const int CHUNK = (NN + 1023) / 1024;
    const int base = t * CHUNK;
    int sum = 0;
    for (int i = 0; i < CHUNK; ++i) {
        int idx = base + i;
        if (idx < NN) sum += g_cnt[idx];
    }
    part[t] = sum;
    __syncthreads();
    for (int d = 1; d < 1024; d <<= 1) {
        int v = (t >= d) ? part[t - d] : 0;
        __syncthreads();
        part[t] += v;
        __syncthreads();
    }
    int run = (t == 0) ? 0 : part[t - 1];
    for (int i = 0; i < CHUNK; ++i) {
        int idx = base + i;
        if (idx < NN) {
            g_off[idx] = run;
            g_cur[idx] = run;
            run += g_cnt[idx];
        }
    }
    if (t == 1023) g_off[NN] = run;
}

__global__ __launch_bounds__(256) void fill_kernel(
    const int* __restrict__ src, const int* __restrict__ dst)
{
    int e = blockIdx.x * 256 + threadIdx.x;
    if (e >= EE) return;
    int pos = atomicAdd(&g_cur[dst[e]], 1);
    g_esrc[pos] = src[e];
    g_pos[e] = pos;
}

// ================= edge kernel (unchanged R16): fp16 A1xB1, double-buffered =================
#define ESM_SIDX  0
#define ESM_A     1024
#define ABUF_SZ   (2 * BM * ALD * 2)
#define ESM_B     (ESM_A + 2 * ABUF_SZ)
#define SBT       (CHK * BLD * 2)
#define BBUF_SZ   (2 * SBT)
#define ESM_PROJE (ESM_B + 2 * BBUF_SZ)
#define ESM_TOTAL (ESM_PROJE + BM * PLD * 4)  // 90112

__global__ __launch_bounds__(256, 2) void edge_kernel(
    const float* __restrict__ e,
    const float* __restrict__ kr,
    const int*  __restrict__ src,
    const int*  __restrict__ dst,
    const float* __restrict__ Eb,
    const float* __restrict__ Rb,
    float* __restrict__ out_e)
{
    extern __shared__ char smem[];
    int*   sidx  = reinterpret_cast<int*>(smem + ESM_SIDX);   // [src 64][dst 64][pos 64]
    float* projR = reinterpret_cast<float*>(smem + ESM_B);
    float* projE = reinterpret_cast<float*>(smem + ESM_PROJE);

    const int tid = threadIdx.x;
    const int wid = tid >> 5;
    const int r0  = blockIdx.x * BM;

    const int bkrow0 = tid >> 4;
    const int bq     = tid & 15;

    {
        uint32_t bdst = (uint32_t)__cvta_generic_to_shared(smem + ESM_B);
#pragma unroll
        for (int it = 0; it < 2; ++it) {
            int krow = bkrow0 + 16 * it;
            size_t goff = (size_t)krow * CD + bq * 8;
            uint32_t soff = (uint32_t)(krow * BLD + bq * 8) * 2;
            cp16(bdst + 0 * SBT + soff, &g_We[0][goff]);
            cp16(bdst + 1 * SBT + soff, &g_We[1][goff]);
        }
        cp_commit();
    }

    if (tid < BM) {
        sidx[tid]          = src[r0 + tid];
        sidx[BM + tid]     = dst[r0 + tid];
        sidx[2 * BM + tid] = g_pos[r0 + tid];
    }

    const int warp_m = wid & 1;
    const int warp_n = wid >> 1;
    const int arow0 = tid >> 3;
    const int aq    = tid & 7;

    wmma::fragment<wmma::accumulator, 16, 16, 16, float> accE[2][2], accR[2][2];
#pragma unroll
    for (int tm = 0; tm < 2; ++tm)
#pragma unroll
        for (int tn = 0; tn < 2; ++tn) {
            wmma::fill_fragment(accE[tm][tn], 0.0f);
            wmma::fill_fragment(accR[tm][tn], 0.0f);
        }

    float4 pve[2], pvk[2];
#pragma unroll
    for (int it = 0; it < 2; ++it) {
        const int row = arow0 + 32 * it;
        pve[it] = *reinterpret_cast<const float4*>(e  + (size_t)(r0 + row) * KDIM + aq * 4);
        pvk[it] = *reinterpret_cast<const float4*>(kr + (size_t)(r0 + row) * KDIM + aq * 4);
    }

    for (int ch = 0; ch < KCH; ++ch) {
        const int ab = ch & 1;
        __half* sAE = reinterpret_cast<__half*>(smem + ESM_A + ab * ABUF_SZ);
        __half* sAK = sAE + BM * ALD;

#pragma unroll
        for (int it = 0; it < 2; ++it) {
            const int row = arow0 + 32 * it;
            const int off = row * ALD + aq * 4;
            __half2* pe2 = reinterpret_cast<__half2*>(sAE + off);
            __half2* pk2 = reinterpret_cast<__half2*>(sAK + off);
            pe2[0] = __halves2half2(__float2half_rn(pve[it].x), __float2half_rn(pve[it].y));
            pe2[1] = __halves2half2(__float2half_rn(pve[it].z), __float2half_rn(pve[it].w));
            pk2[0] = __halves2half2(__float2half_rn(pvk[it].x), __float2half_rn(pvk[it].y));
            pk2[1] = __halves2half2(__float2half_rn(pvk[it].z), __float2half_rn(pvk[it].w));
        }
        if (ch < KCH - 1) {
            const int gk = (ch + 1) * CHK + aq * 4;
#pragma unroll
            for (int it = 0; it < 2; ++it) {
                const int row = arow0 + 32 * it;
                pve[it] = *reinterpret_cast<const float4*>(e  + (size_t)(r0 + row) * KDIM + gk);
                pvk[it] = *reinterpret_cast<const float4*>(kr + (size_t)(r0 + row) * KDIM + gk);
            }
        }

        cp_wait_all();
        __syncthreads();

        if (ch < KCH - 1) {
            uint32_t bdst = (uint32_t)__cvta_generic_to_shared(
                smem + ESM_B + ((ch + 1) & 1) * BBUF_SZ);
#pragma unroll
            for (int it = 0; it < 2; ++it) {
                int krow = bkrow0 + 16 * it;
                size_t goff = (size_t)((ch + 1) * CHK + krow) * CD + bq * 8;
                uint32_t soff = (uint32_t)(krow * BLD + bq * 8) * 2;
                cp16(bdst + 0 * SBT + soff, &g_We[0][goff]);
                cp16(bdst + 1 * SBT + soff, &g_We[1][goff]);
            }
            cp_commit();
        }

        __half* sB  = reinterpret_cast<__half*>(smem + ESM_B + ab * BBUF_SZ);
        __half* sBE = sB;
        __half* sBR = sB + SBT / 2;

#pragma unroll
        for (int ks = 0; ks < 2; ++ks) {
            wmma::fragment<wmma::matrix_a, 16, 16, 16, __half, wmma::row_major> a[2];
            wmma::fragment<wmma::matrix_b, 16, 16, 16, __half, wmma::row_major> b[2];
#pragma unroll
            for (int tm = 0; tm < 2; ++tm)
                wmma::load_matrix_sync(a[tm], sAE + (warp_m * 32 + tm * 16) * ALD + ks * 16, ALD);
#pragma unroll
            for (int tn = 0; tn < 2; ++tn)
                wmma::load_matrix_sync(b[tn], sBE + ks * 16 * BLD + warp_n * 32 + tn * 16, BLD);
#pragma unroll
            for (int tm = 0; tm < 2; ++tm)
#pragma unroll
                for (int tn = 0; tn < 2; ++tn)
                    wmma::mma_sync(accE[tm][tn], a[tm], b[tn], accE[tm][tn]);
#pragma unroll
            for (int tm = 0; tm < 2; ++tm)
                wmma::load_matrix_sync(a[tm], sAK + (warp_m * 32 + tm * 16) * ALD + ks * 16, ALD);
#pragma unroll
            for (int tn = 0; tn < 2; ++tn)
                wmma::load_matrix_sync(b[tn], sBR + ks * 16 * BLD + warp_n * 32 + tn * 16, BLD);
#pragma unroll
            for (int tm = 0; tm < 2; ++tm)
#pragma unroll
                for (int tn = 0; tn < 2; ++tn)
                    wmma::mma_sync(accR[tm][tn], a[tm], b[tn], accR[tm][tn]);
        }
    }

    __syncthreads();
#pragma unroll
    for (int tm = 0; tm < 2; ++tm)
#pragma unroll
        for (int tn = 0; tn < 2; ++tn) {
            const int po = (warp_m * 32 + tm * 16) * PLD + warp_n * 32 + tn * 16;
            wmma::store_matrix_sync(projR + po, accR[tm][tn], PLD, wmma::mem_row_major);
            wmma::store_matrix_sync(projE + po, accE[tm][tn], PLD, wmma::mem_row_major);
        }
    __syncthreads();

    const int erow    = tid & 63;
    const int quarter = tid >> 6;
    const int cc      = quarter * 32;

    const int gedge = r0 + erow;
    const int sn  = sidx[erow];
    const int dn  = sidx[BM + erow];
    const int pos = sidx[2 * BM + erow];

    const __half* Kp = g_Kh + (size_t)sn * CD + cc;
    const __half* Qp = g_Qh + (size_t)dn * CD + cc;

    float s0 = 0.f, s1 = 0.f;
    float* oe = out_e + (size_t)gedge * CD + cc;
#pragma unroll
    for (int q = 0; q < 8; ++q) {
        float4 rv  = *reinterpret_cast<const float4*>(projR + erow * PLD + cc + q * 4);
        float4 rbv = *reinterpret_cast<const float4*>(Rb + cc + q * 4);
        float4 ev  = *reinterpret_cast<const float4*>(projE + erow * PLD + cc + q * 4);
        float4 ebv = *reinterpret_cast<const float4*>(Eb + cc + q * 4);
        uint2 ku = *reinterpret_cast<const uint2*>(Kp + q * 4);
        uint2 qu = *reinterpret_cast<const uint2*>(Qp + q * 4);
        float2 k01 = __half22float2(*reinterpret_cast<const __half2*>(&ku.x));
        float2 k23 = __half22float2(*reinterpret_cast<const __half2*>(&ku.y));
        float2 q01 = __half22float2(*reinterpret_cast<const __half2*>(&qu.x));
        float2 q23 = __half22float2(*reinterpret_cast<const __half2*>(&qu.y));
        const float pr[4] = {rv.x + rbv.x, rv.y + rbv.y, rv.z + rbv.z, rv.w + rbv.w};
        const float pe[4] = {ev.x + ebv.x, ev.y + ebv.y, ev.z + ebv.z, ev.w + ebv.w};
        const float kk[4] = {k01.x, k01.y, k23.x, k23.y};
        const float qq[4] = {q01.x, q01.y, q23.x, q23.y};
        float sc[4];
#pragma unroll
        for (int j = 0; j < 4; ++j) {
            float t = fmaf(kk[j] * qq[j], 0.25f, pr[j]) * pe[j];
            sc[j] = t;
            if (q < 4) s0 += t; else s1 += t;
        }
        __stcs(reinterpret_cast<float4*>(oe + q * 4), make_float4(sc[0], sc[1], sc[2], sc[3]));
    }

    s0 = __expf(fminf(fmaxf(s0, -5.0f), 5.0f));
    s1 = __expf(fminf(fmaxf(s1, -5.0f), 5.0f));

    *reinterpret_cast<float2*>(&g_s[(size_t)pos * NH + quarter * 2]) = make_float2(s0, s1);
}

// ================= gather kernel: one warp per node, fp16 V =================
__global__ __launch_bounds__(256) void gather_kernel(float* __restrict__ out_h)
{
    const int node = (blockIdx.x * 256 + threadIdx.x) >> 5;
    const int lane = threadIdx.x & 31;
    if (node >= NN) return;

    const int off0 = g_off[node];
    const int off1 = g_off[node + 1];
    const int head = lane >> 2;

    float4 acc = make_float4(0.f, 0.f, 0.f, 0.f);
    float zs = 0.f;

    int i = off0;
    for (; i + 2 <= off1; i += 2) {
        int   n0 = g_esrc[i];
        int   n1 = g_esrc[i + 1];
        float w0 = g_s[(size_t)i * NH + head];
        float w1 = g_s[(size_t)(i + 1) * NH + head];
        uint2 u0 = __ldg(reinterpret_cast<const uint2*>(g_Vh + (size_t)n0 * CD + lane * 4));
        uint2 u1 = __ldg(reinterpret_cast<const uint2*>(g_Vh + (size_t)n1 * CD + lane * 4));
        float2 a0 = __half22float2(*reinterpret_cast<const __half2*>(&u0.x));
        float2 b0 = __half22float2(*reinterpret_cast<const __half2*>(&u0.y));
        float2 a1 = __half22float2(*reinterpret_cast<const __half2*>(&u1.x));
        float2 b1 = __half22float2(*reinterpret_cast<const __half2*>(&u1.y));
        acc.x = fmaf(w0, a0.x, acc.x); acc.y = fmaf(w0, a0.y, acc.y);
        acc.z = fmaf(w0, b0.x, acc.z); acc.w = fmaf(w0, b0.y, acc.w);
        acc.x = fmaf(w1, a1.x, acc.x); acc.y = fmaf(w1, a1.y, acc.y);
        acc.z = fmaf(w1, b1.x, acc.z); acc.w = fmaf(w1, b1.y, acc.w);
        zs += w0 + w1;
    }
    if (i < off1) {
        int   n0 = g_esrc[i];
        float w = g_s[(size_t)i * NH + head];
        uint2 u0 = __ldg(reinterpret_cast<const uint2*>(g_Vh + (size_t)n0 * CD + lane * 4));
        float2 a0 = __half22float2(*reinterpret_cast<const __half2*>(&u0.x));
        float2 b0 = __half22float2(*reinterpret_cast<const __half2*>(&u0.y));
        acc.x = fmaf(w, a0.x, acc.x); acc.y = fmaf(w, a0.y, acc.y);
        acc.z = fmaf(w, b0.x, acc.z); acc.w = fmaf(w, b0.y, acc.w);
        zs += w;
    }

    float inv = 1.0f / (zs + 1e-6f);
    acc.x *= inv; acc.y *= inv; acc.z *= inv; acc.w *= inv;
    *reinterpret_cast<float4*>(out_h + (size_t)node * CD + lane * 4) = acc;
}

// ================= node kernel: fp16 A1xB1, all three projections =================
#define NSM_A    0
#define NSM_B    (64 * AFULL * 2)             // A: 17408
#define NSM_TOTAL (NSM_B + KDIM * BLD * 2)    // + B 34816 = 52224
// proj (64*PLD*4 = 33792) aliases the B region (34816)

__global__ __launch_bounds__(256, 3) void node_proj_qkv_kernel(
    const float* __restrict__ h,
    const float* __restrict__ Qb, const float* __restrict__ Kb, const float* __restrict__ Vb,
    __half* __restrict__ outQ, __half* __restrict__ outK, __half* __restrict__ outV)
{
    extern __shared__ char smem[];
    __half* sA   = reinterpret_cast<__half*>(smem + NSM_A);
    __half* sB   = reinterpret_cast<__half*>(smem + NSM_B);
    float*  proj = reinterpret_cast<float*>(smem + NSM_B);   // alias

    const int tid = threadIdx.x;
    const int wid = tid >> 5;
    const int r0  = blockIdx.x * 64;

    // A: h rows -> fp16, 8 float4 per thread
    for (int i = tid; i < 64 * 32; i += 256) {
        int row = i >> 5, kq = i & 31;
        float4 v = make_float4(0.f, 0.f, 0.f, 0.f);
        if (r0 + row < NN)
            v = reinterpret_cast<const float4*>(h + (size_t)(r0 + row) * KDIM)[kq];
        __half2 h01 = __floats2half2_rn(v.x, v.y);
        __half2 h23 = __floats2half2_rn(v.z, v.w);
        uint2 pk;
        pk.x = *reinterpret_cast<uint32_t*>(&h01);
        pk.y = *reinterpret_cast<uint32_t*>(&h23);
        *reinterpret_cast<uint2*>(sA + row * AFULL + kq * 4) = pk;
    }

    const float* Bs[3] = {Qb, Kb, Vb};
    __half* Os[3] = {outQ, outK, outV};

    const int warp_m = wid & 1;
    const int warp_n = wid >> 1;

    for (int m = 0; m < 3; ++m) {
        __syncthreads();   // A ready (m=0) / prior proj reads done (m>0)
        for (int i = tid; i < KDIM * (CD / 8); i += 256) {
            int krow = i >> 4, q = i & 15;
            size_t goff = (size_t)krow * CD + q * 8;
            int soff = krow * BLD + q * 8;
            *reinterpret_cast<uint4*>(sB + soff) =
                *reinterpret_cast<const uint4*>(&g_We[2 + m][goff]);
        }
        __syncthreads();

        wmma::fragment<wmma::accumulator, 16, 16, 16, float> acc[2][2];
#pragma unroll
        for (int tm = 0; tm < 2; ++tm)
#pragma unroll
            for (int tn = 0; tn < 2; ++tn) wmma::fill_fragment(acc[tm][tn], 0.0f);

#pragma unroll
        for (int ks = 0; ks < KDIM / 16; ++ks) {
            wmma::fragment<wmma::matrix_a, 16, 16, 16, __half, wmma::row_major> a[2];
            wmma::fragment<wmma::matrix_b, 16, 16, 16, __half, wmma::row_major> b[2];
#pragma unroll
            for (int tm = 0; tm < 2; ++tm)
                wmma::load_matrix_sync(a[tm], sA + (warp_m * 32 + tm * 16) * AFULL + ks * 16, AFULL);
#pragma unroll
            for (int tn = 0; tn < 2; ++tn)
                wmma::load_matrix_sync(b[tn], sB + ks * 16 * BLD + warp_n * 32 + tn * 16, BLD);
#pragma unroll
            for (int tm = 0; tm < 2; ++tm)
#pragma unroll
                for (int tn = 0; tn < 2; ++tn)
                    wmma::mma_sync(acc[tm][tn], a[tm], b[tn], acc[tm][tn]);
        }

        __syncthreads();   // MMAs done reading B before proj overwrites
#pragma unroll
        for (int tm = 0; tm < 2; ++tm)
#pragma unroll
            for (int tn = 0; tn < 2; ++tn)
                wmma::store_matrix_sync(proj + (warp_m * 32 + tm * 16) * PLD + warp_n * 32 + tn * 16,
                                        acc[tm][tn], PLD, wmma::mem_row_major);
        __syncthreads();

        const int row = tid >> 2;
        const int cq  = (tid & 3) * 32;
        if (r0 + row < NN) {
            __half* out = Os[m] + (size_t)(r0 + row) * CD + cq;
#pragma unroll
            for (int q = 0; q < 8; ++q) {
                float4 v  = *reinterpret_cast<const float4*>(proj + row * PLD + cq + q * 4);
                float4 bv = *reinterpret_cast<const float4*>(Bs[m] + cq + q * 4);
                __half2 h01 = __floats2half2_rn(v.x + bv.x, v.y + bv.y);
                __half2 h23 = __floats2half2_rn(v.z + bv.z, v.w + bv.w);
                uint2 pk;
                pk.x = *reinterpret_cast<uint32_t*>(&h01);
                pk.y = *reinterpret_cast<uint32_t*>(&h23);
                *reinterpret_cast<uint2*>(out + q * 4) = pk;
            }
        }
    }
}

// ---------------- launch ----------------
extern "C" void kernel_launch(void* const* d_in, const int* in_sizes, int n_in,
                              void* d_out, int out_size)
{
    const float* h   = (const float*)d_in[0];
    const float* e   = (const float*)d_in[1];
    const float* kr  = (const float*)d_in[2];
    const int*   src = (const int*)  d_in[3];
    const int*   dst = (const int*)  d_in[4];
    const float* Qw  = (const float*)d_in[5];
    const float* Qb  = (const float*)d_in[6];
    const float* Kw  = (const float*)d_in[7];
    const float* Kb  = (const float*)d_in[8];
    const float* Vw  = (const float*)d_in[9];
    const float* Vb  = (const float*)d_in[10];
    const float* Ew  = (const float*)d_in[11];
    const float* Eb  = (const float*)d_in[12];
    const float* Rw  = (const float*)d_in[13];
    const float* Rb  = (const float*)d_in[14];

    float* out_h = (float*)d_out;
    float* out_e = (float*)d_out + (size_t)NN * CD;

    cudaFuncSetAttribute(node_proj_qkv_kernel, cudaFuncAttributeMaxDynamicSharedMemorySize, NSM_TOTAL);
    cudaFuncSetAttribute(edge_kernel,          cudaFuncAttributeMaxDynamicSharedMemorySize, ESM_TOTAL);

    void* cp = nullptr;
    cudaGetSymbolAddress(&cp, g_cnt);
    cudaMemsetAsync(cp, 0, NN * sizeof(int));

    void *qp, *kp, *vp;
    cudaGetSymbolAddress(&qp, g_Qh);
    cudaGetSymbolAddress(&kp, g_Kh);
    cudaGetSymbolAddress(&vp, g_Vh);

    convert_weights_kernel<<<(KDIM * CD + 255) / 256, 256>>>(Ew, Rw, Qw, Kw, Vw);

    hist_kernel<<<(EE + 255) / 256, 256>>>(dst);
    scan_kernel<<<1, 1024>>>();
    fill_kernel<<<(EE + 255) / 256, 256>>>(src, dst);

    const int nodeBlocks = (NN + 63) / 64;  // 782
    node_proj_qkv_kernel<<<nodeBlocks, 256, NSM_TOTAL>>>(
        h, Qb, Kb, Vb, (__half*)qp, (__half*)kp, (__half*)vp);

    edge_kernel<<<EE / BM, 256, ESM_TOTAL>>>(e, kr, src, dst, Eb, Rb, out_e);

    gather_kernel<<<(NN * 32 + 255) / 256, 256>>>(out_h);
}